// round 2
// baseline (speedup 1.0000x reference)
#include <cuda_runtime.h>
#include <cstdint>

// ---------------------------------------------------------------------------
// FP8Linear: out[M,N] = x[M,K] @ (qweight*scales)^T + bias
// M=8192, N=16384, K=4096, group=128.
// Legacy-path tf32 mma.sync GEMM (tcgen05 unavailable: harness compiles PTX at
// compute_103 base, all 'a'-features rejected by ptxas).
// CTA tile 128x128x32, 8 warps (warp tile 64x32), 3-stage cp.async pipeline.
// ---------------------------------------------------------------------------

#define M_ALL 8192
#define N_ALL 16384
#define K_ALL 4096
#define TM 128
#define TN 128
#define TK 32
#define THREADS 256
#define NKT (K_ALL / TK)            // 128
#define NSTAGES 3
#define A_TILE_BYTES (TM * TK * 4)  // 16384
#define B_TILE_BYTES (TN * TK * 4)  // 16384
#define STAGE_BYTES (A_TILE_BYTES + B_TILE_BYTES)  // 32768
#define SMEM_TOTAL (NSTAGES * STAGE_BYTES)         // 98304

// ---------------- PTX helpers ----------------
__device__ __forceinline__ uint32_t tf32_of(float f) {
    uint32_t r;
    asm("cvt.rna.tf32.f32 %0, %1;" : "=r"(r) : "f"(f));
    return r;
}

__device__ __forceinline__ void cp_async16(uint32_t smem_dst, const void* gsrc) {
    asm volatile("cp.async.cg.shared.global [%0], [%1], 16;"
                 :: "r"(smem_dst), "l"(__cvta_generic_to_global(gsrc))
                 : "memory");
}
#define CP_COMMIT() asm volatile("cp.async.commit_group;" ::: "memory")
#define CP_WAIT1()  asm volatile("cp.async.wait_group 1;" ::: "memory")

__device__ __forceinline__ void mma_tf32(float* c, const uint32_t* a,
                                         const uint32_t* b) {
    asm volatile(
        "mma.sync.aligned.m16n8k8.row.col.f32.tf32.tf32.f32 "
        "{%0,%1,%2,%3}, {%4,%5,%6,%7}, {%8,%9}, {%0,%1,%2,%3};"
        : "+f"(c[0]), "+f"(c[1]), "+f"(c[2]), "+f"(c[3])
        : "r"(a[0]), "r"(a[1]), "r"(a[2]), "r"(a[3]),
          "r"(b[0]), "r"(b[1]));
}

extern __shared__ __align__(1024) char smem_raw[];

// ------------- tile load: gmem -> swizzled smem via cp.async -------------
// Layout per tile: row-major [row][32 floats] = 128B/row; 16B chunk j of row r
// stored at chunk (j ^ (r&7)) -> conflict-free fragment reads.
__device__ __forceinline__ void load_tile(const float* __restrict__ Abase,
                                          const float* __restrict__ Bbase,
                                          int kt, char* stage, int tid) {
    char* As = stage;
    char* Bs = stage + A_TILE_BYTES;
    #pragma unroll
    for (int i = 0; i < 4; i++) {
        int id = tid + i * THREADS;
        int row = id >> 3, j = id & 7;
        const float* src = Abase + (size_t)row * K_ALL + kt * TK + j * 4;
        uint32_t dst = (uint32_t)__cvta_generic_to_shared(
            As + row * 128 + ((j ^ (row & 7)) << 4));
        cp_async16(dst, src);
    }
    #pragma unroll
    for (int i = 0; i < 4; i++) {
        int id = tid + i * THREADS;
        int row = id >> 3, j = id & 7;
        const float* src = Bbase + (size_t)row * K_ALL + kt * TK + j * 4;
        uint32_t dst = (uint32_t)__cvta_generic_to_shared(
            Bs + row * 128 + ((j ^ (row & 7)) << 4));
        cp_async16(dst, src);
    }
}

// ---------------- kernel ----------------
__global__ void __launch_bounds__(THREADS, 2)
fp8linear_mma_kernel(const float* __restrict__ X,
                     const float* __restrict__ W,
                     const float* __restrict__ S,
                     const float* __restrict__ BIAS,
                     float* __restrict__ OUT) {
    const int tid = threadIdx.x;
    const int lane = tid & 31;
    const int wid = tid >> 5;
    const int wm = wid & 1;        // warp m: 0..1  (64 rows each)
    const int wn = wid >> 1;       // warp n: 0..3  (32 cols each)
    const int g = lane >> 2;       // groupID 0..7
    const int tig = lane & 3;      // thread-in-group 0..3

    // CTA rasterization: GROUP_M=16 -> wave working set ~54MB < L2
    int pid = blockIdx.x;
    int group = pid >> 11;                 // / (16*128)
    int pid_loc = pid & 2047;
    int pid_m = group * 16 + (pid_loc & 15);
    int pid_n = pid_loc >> 4;

    const float* Abase = X + (size_t)pid_m * TM * K_ALL;
    const float* Bbase = W + (size_t)pid_n * TN * K_ALL;

    // accumulators: 4 mtiles x 4 ntiles x 4 regs
    float acc[4][4][4];
    #pragma unroll
    for (int i = 0; i < 4; i++)
        #pragma unroll
        for (int j = 0; j < 4; j++)
            #pragma unroll
            for (int q = 0; q < 4; q++) acc[i][j][q] = 0.0f;

    // prologue: stages 0,1
    load_tile(Abase, Bbase, 0, smem_raw, tid);
    CP_COMMIT();
    load_tile(Abase, Bbase, 1, smem_raw + STAGE_BYTES, tid);
    CP_COMMIT();

    float sc[4];  // per-lane dequant scales for 4 n-tiles, current group

    for (int kt = 0; kt < NKT; kt++) {
        CP_WAIT1();
        __syncthreads();
        if (kt + 2 < NKT)
            load_tile(Abase, Bbase, kt + 2,
                      smem_raw + ((kt + 2) % NSTAGES) * STAGE_BYTES, tid);
        CP_COMMIT();

        if ((kt & 3) == 0) {
            int grp = kt >> 2;
            #pragma unroll
            for (int j = 0; j < 4; j++) {
                int n_glob = pid_n * TN + wn * 32 + j * 8 + g;
                sc[j] = __ldg(S + (size_t)n_glob * 32 + grp);
            }
        }

        const char* As = smem_raw + (kt % NSTAGES) * STAGE_BYTES;
        const char* Bs = As + A_TILE_BYTES;

        #pragma unroll
        for (int s = 0; s < 4; s++) {
            const int co0 = ((2 * s) ^ g) << 4;
            const int co1 = ((2 * s + 1) ^ g) << 4;

            uint32_t afr[4][4];
            #pragma unroll
            for (int i = 0; i < 4; i++) {
                const char* base = As + (wm * 64 + i * 16 + g) * 128 + tig * 4;
                afr[i][0] = tf32_of(*(const float*)(base + co0));
                afr[i][1] = tf32_of(*(const float*)(base + 1024 + co0));
                afr[i][2] = tf32_of(*(const float*)(base + co1));
                afr[i][3] = tf32_of(*(const float*)(base + 1024 + co1));
            }
            uint32_t bfr[4][2];
            #pragma unroll
            for (int j = 0; j < 4; j++) {
                const char* base = Bs + (wn * 32 + j * 8 + g) * 128 + tig * 4;
                bfr[j][0] = tf32_of(*(const float*)(base + co0) * sc[j]);
                bfr[j][1] = tf32_of(*(const float*)(base + co1) * sc[j]);
            }
            #pragma unroll
            for (int i = 0; i < 4; i++)
                #pragma unroll
                for (int j = 0; j < 4; j++)
                    mma_tf32(acc[i][j], afr[i], bfr[j]);
        }
    }

    // ---------------- epilogue: bias + store ----------------
    #pragma unroll
    for (int j = 0; j < 4; j++) {
        int col = pid_n * TN + wn * 32 + j * 8 + tig * 2;
        float2 bb = *(const float2*)(BIAS + col);
        #pragma unroll
        for (int i = 0; i < 4; i++) {
            int row0 = pid_m * TM + wm * 64 + i * 16 + g;
            float2 o0, o1;
            o0.x = acc[i][j][0] + bb.x;
            o0.y = acc[i][j][1] + bb.y;
            o1.x = acc[i][j][2] + bb.x;
            o1.y = acc[i][j][3] + bb.y;
            *(float2*)(OUT + (size_t)row0 * N_ALL + col) = o0;
            *(float2*)(OUT + (size_t)(row0 + 8) * N_ALL + col) = o1;
        }
    }
}

// ---------------- launch ----------------
extern "C" void kernel_launch(void* const* d_in, const int* in_sizes, int n_in,
                              void* d_out, int out_size) {
    const float* x = (const float*)d_in[0];      // [4,2048,4096]
    const float* qw = (const float*)d_in[1];     // [16384,4096]
    const float* sc = (const float*)d_in[2];     // [16384,32]
    const float* bias = (const float*)d_in[3];   // [16384]
    float* out = (float*)d_out;                  // [4,2048,16384]

    cudaFuncSetAttribute(fp8linear_mma_kernel,
                         cudaFuncAttributeMaxDynamicSharedMemorySize, SMEM_TOTAL);
    int grid = (M_ALL / TM) * (N_ALL / TN);      // 64 * 128 = 8192
    fp8linear_mma_kernel<<<grid, THREADS, SMEM_TOTAL>>>(x, qw, sc, bias, out);
}

// round 4
// speedup vs baseline: 2.6567x; 2.6567x over previous
#include <cuda_runtime.h>
#include <cuda_fp16.h>
#include <cstdint>

// ---------------------------------------------------------------------------
// FP8Linear: out[M,N] = x[M,K] @ (qweight*scales)^T + bias
// M=8192, N=16384, K=4096, group=128.
// R4: R3 design (fp16 m16n8k16, fragment-packed prep) with the prep_w chunk-id
// decode fixed (kt at bit 9, nb at bit 16 -- R3 skipped bit 9, scrambling Wp).
// ---------------------------------------------------------------------------

#define M_ALL 8192
#define N_ALL 16384
#define K_ALL 4096
#define TM 128
#define TN 128
#define TK 32
#define THREADS 256
#define NKT (K_ALL / TK)              // 128
#define NSTAGES 4
#define STAGE_BYTES 16384             // A 8KB + B 8KB (fp16)
#define SMEM_TOTAL (NSTAGES * STAGE_BYTES)  // 65536

// Packed operand scratch (fragment-major, fp16).
// A' chunk (mb,kt,it,s,lane): 4x uint32 = one m16n8k16 A fragment for lane.
//   reg q = {A[m,k],A[m,k+1]}, m = mb*128+it*16+(q&1)*8+g, k = kt*32+s*16+2*tig+(q>>1)*8
// B' chunk (nb,kt,jt,lane): q=2s+r -> {B[n,k],B[n,k+1]}, n = nb*128+jt*8+g,
//   k = kt*32+s*16+2*tig+r*8
__device__ uint4 Xp[64ull * 128 * 8 * 2 * 32];     //  64 MB
__device__ uint4 Wp[128ull * 128 * 16 * 32];       // 128 MB

// ---------------- helpers ----------------
__device__ __forceinline__ void cp_async16(uint32_t smem_dst, const void* gsrc) {
    asm volatile("cp.async.cg.shared.global [%0], [%1], 16;"
                 :: "r"(smem_dst), "l"(__cvta_generic_to_global(gsrc))
                 : "memory");
}
#define CP_COMMIT() asm volatile("cp.async.commit_group;" ::: "memory")
#define CP_WAIT2()  asm volatile("cp.async.wait_group 2;" ::: "memory")

__device__ __forceinline__ void mma_f16(float* c, const uint32_t* a,
                                        uint32_t b0, uint32_t b1) {
    asm volatile(
        "mma.sync.aligned.m16n8k16.row.col.f32.f16.f16.f32 "
        "{%0,%1,%2,%3}, {%4,%5,%6,%7}, {%8,%9}, {%0,%1,%2,%3};"
        : "+f"(c[0]), "+f"(c[1]), "+f"(c[2]), "+f"(c[3])
        : "r"(a[0]), "r"(a[1]), "r"(a[2]), "r"(a[3]), "r"(b0), "r"(b1));
}

__device__ __forceinline__ uint32_t h2(float lo, float hi) {
    __half2 h = __floats2half2_rn(lo, hi);
    return *(uint32_t*)&h;
}

// ---------------- prep kernels ----------------
// prep_X: one thread per A' 16B chunk (2^22 threads)
// cid fields: lane[0:5) s[5] it[6:9) kt[9:16) mb[16:22)
__global__ void __launch_bounds__(256)
prep_x_kernel(const float* __restrict__ X) {
    uint32_t cid = blockIdx.x * 256 + threadIdx.x;
    int lane = cid & 31;
    int s    = (cid >> 5) & 1;
    int it   = (cid >> 6) & 7;
    int kt   = (cid >> 9) & 127;
    int mb   = cid >> 16;
    int g = lane >> 2, tig = lane & 3;
    int m0 = mb * 128 + it * 16 + g;
    int k0 = kt * 32 + s * 16 + 2 * tig;
    const float* p0 = X + (size_t)m0 * K_ALL + k0;
    const float* p1 = X + (size_t)(m0 + 8) * K_ALL + k0;
    float2 v0 = *(const float2*)(p0);
    float2 v1 = *(const float2*)(p1);
    float2 v2 = *(const float2*)(p0 + 8);
    float2 v3 = *(const float2*)(p1 + 8);
    uint4 out;
    out.x = h2(v0.x, v0.y);
    out.y = h2(v1.x, v1.y);
    out.z = h2(v2.x, v2.y);
    out.w = h2(v3.x, v3.y);
    Xp[cid] = out;
}

// prep_W: one thread per B' 16B chunk (2^23 threads), scale folded in
// cid fields: lane[0:5) jt[5:9) kt[9:16) nb[16:23)   (R3 bug: used >>10 / >>17)
__global__ void __launch_bounds__(256)
prep_w_kernel(const float* __restrict__ W, const float* __restrict__ S) {
    uint32_t cid = blockIdx.x * 256 + threadIdx.x;
    int lane = cid & 31;
    int jt   = (cid >> 5) & 15;
    int kt   = (cid >> 9) & 127;
    int nb   = cid >> 16;
    int g = lane >> 2, tig = lane & 3;
    int n  = nb * 128 + jt * 8 + g;
    int kb = kt * 32 + 2 * tig;
    float sc = __ldg(S + (size_t)n * 32 + (kt >> 2));  // group const per kt
    const float* p = W + (size_t)n * K_ALL + kb;
    float2 v0 = *(const float2*)(p);         // k = kb      (s0,r0)
    float2 v1 = *(const float2*)(p + 8);     // k = kb + 8  (s0,r1)
    float2 v2 = *(const float2*)(p + 16);    // k = kb + 16 (s1,r0)
    float2 v3 = *(const float2*)(p + 24);    // k = kb + 24 (s1,r1)
    uint4 out;
    out.x = h2(v0.x * sc, v0.y * sc);
    out.y = h2(v1.x * sc, v1.y * sc);
    out.z = h2(v2.x * sc, v2.y * sc);
    out.w = h2(v3.x * sc, v3.y * sc);
    Wp[cid] = out;
}

// ---------------- GEMM ----------------
extern __shared__ __align__(1024) char smem_raw[];

__device__ __forceinline__ void load_tile(const uint4* __restrict__ Ablk,
                                          const uint4* __restrict__ Bblk,
                                          char* stage, int tid) {
    uint32_t sb = (uint32_t)__cvta_generic_to_shared(stage);
    cp_async16(sb + tid * 16,            Ablk + tid);
    cp_async16(sb + (tid + 256) * 16,    Ablk + tid + 256);
    cp_async16(sb + (tid + 512) * 16,    Bblk + tid);
    cp_async16(sb + (tid + 768) * 16,    Bblk + tid + 256);
}

__global__ void __launch_bounds__(THREADS, 2)
fp8linear_hmma_kernel(const float* __restrict__ BIAS,
                      float* __restrict__ OUT) {
    const int tid = threadIdx.x;
    const int lane = tid & 31;
    const int wid = tid >> 5;
    const int wm = wid & 1;        // 2 x 64 rows
    const int wn = wid >> 1;       // 4 x 32 cols
    const int g = lane >> 2;
    const int tig = lane & 3;

    // rasterization: GROUP_M=16
    int pid = blockIdx.x;
    int group = pid >> 11;
    int pid_loc = pid & 2047;
    int pid_m = group * 16 + (pid_loc & 15);
    int pid_n = pid_loc >> 4;

    const uint4* Abase = Xp + (size_t)pid_m * 128 * 512;   // 512 uint4 per kt
    const uint4* Bbase = Wp + (size_t)pid_n * 128 * 512;

    float acc[4][4][4];
    #pragma unroll
    for (int i = 0; i < 4; i++)
        #pragma unroll
        for (int j = 0; j < 4; j++)
            #pragma unroll
            for (int q = 0; q < 4; q++) acc[i][j][q] = 0.0f;

    // prologue: stages 0..2
    #pragma unroll
    for (int p = 0; p < 3; p++) {
        load_tile(Abase + p * 512, Bbase + p * 512,
                  smem_raw + p * STAGE_BYTES, tid);
        CP_COMMIT();
    }

    for (int kt = 0; kt < NKT; kt++) {
        CP_WAIT2();
        __syncthreads();
        if (kt + 3 < NKT)
            load_tile(Abase + (kt + 3) * 512, Bbase + (kt + 3) * 512,
                      smem_raw + ((kt + 3) & 3) * STAGE_BYTES, tid);
        CP_COMMIT();

        const char* stg = smem_raw + (kt & 3) * STAGE_BYTES;
        const uint4* As = (const uint4*)stg;                 // 512 chunks
        const uint4* Bs = (const uint4*)(stg + 8192);

        // B fragments: one v4 per n8-tile covers both k16 steps
        uint4 bfr[4];
        #pragma unroll
        for (int j = 0; j < 4; j++)
            bfr[j] = Bs[(wn * 4 + j) * 32 + lane];

        #pragma unroll
        for (int s = 0; s < 2; s++) {
            uint4 afr[4];
            #pragma unroll
            for (int i = 0; i < 4; i++)
                afr[i] = As[(((wm * 4 + i) * 2) + s) * 32 + lane];
            #pragma unroll
            for (int i = 0; i < 4; i++) {
                #pragma unroll
                for (int j = 0; j < 4; j++) {
                    uint32_t b0 = s ? bfr[j].z : bfr[j].x;
                    uint32_t b1 = s ? bfr[j].w : bfr[j].y;
                    mma_f16(acc[i][j], (const uint32_t*)&afr[i], b0, b1);
                }
            }
        }
    }

    // ---------------- epilogue: bias + store ----------------
    #pragma unroll
    for (int j = 0; j < 4; j++) {
        int col = pid_n * TN + wn * 32 + j * 8 + tig * 2;
        float2 bb = *(const float2*)(BIAS + col);
        #pragma unroll
        for (int i = 0; i < 4; i++) {
            int row0 = pid_m * TM + wm * 64 + i * 16 + g;
            float2 o0, o1;
            o0.x = acc[i][j][0] + bb.x;
            o0.y = acc[i][j][1] + bb.y;
            o1.x = acc[i][j][2] + bb.x;
            o1.y = acc[i][j][3] + bb.y;
            *(float2*)(OUT + (size_t)row0 * N_ALL + col) = o0;
            *(float2*)(OUT + (size_t)(row0 + 8) * N_ALL + col) = o1;
        }
    }
}

// ---------------- launch ----------------
extern "C" void kernel_launch(void* const* d_in, const int* in_sizes, int n_in,
                              void* d_out, int out_size) {
    const float* x = (const float*)d_in[0];      // [4,2048,4096]
    const float* qw = (const float*)d_in[1];     // [16384,4096]
    const float* sc = (const float*)d_in[2];     // [16384,32]
    const float* bias = (const float*)d_in[3];   // [16384]
    float* out = (float*)d_out;                  // [4,2048,16384]

    prep_x_kernel<<<4194304 / 256, 256>>>(x);
    prep_w_kernel<<<8388608 / 256, 256>>>(qw, sc);

    cudaFuncSetAttribute(fp8linear_hmma_kernel,
                         cudaFuncAttributeMaxDynamicSharedMemorySize, SMEM_TOTAL);
    int grid = (M_ALL / TM) * (N_ALL / TN);      // 8192
    fp8linear_hmma_kernel<<<grid, THREADS, SMEM_TOTAL>>>(bias, out);
}

// round 5
// speedup vs baseline: 3.1087x; 1.1702x over previous
#include <cuda_runtime.h>
#include <cuda_fp16.h>
#include <cstdint>

// ---------------------------------------------------------------------------
// FP8Linear: out[M,N] = x[M,K] @ (qweight*scales)^T + bias
// M=8192, N=16384, K=4096, group=128.
// R5: warp tile 64x32 -> 64x64 (4 warps/CTA). Cuts smem crossbar traffic per
// MMA by 25% (A replication 4x->2x); HMMA becomes the binding pipe.
// ---------------------------------------------------------------------------

#define M_ALL 8192
#define N_ALL 16384
#define K_ALL 4096
#define TM 128
#define TN 128
#define TK 32
#define THREADS 128
#define NKT (K_ALL / TK)              // 128
#define NSTAGES 4
#define STAGE_BYTES 16384             // A 8KB + B 8KB (fp16)
#define SMEM_TOTAL (NSTAGES * STAGE_BYTES)  // 65536

// Packed operand scratch (fragment-major, fp16) -- layout unchanged from R4.
// A' chunk (mb,kt,it,s,lane): regs x/y/z/w = {m=g,k0},{m=g+8,k0},{m=g,k0+8},{m=g+8,k0+8}
// B' chunk (nb,kt,jt,lane):   regs x/y/z/w = (s0,r0),(s0,r1),(s1,r0),(s1,r1)
__device__ uint4 Xp[64ull * 128 * 8 * 2 * 32];     //  64 MB
__device__ uint4 Wp[128ull * 128 * 16 * 32];       // 128 MB

// ---------------- helpers ----------------
__device__ __forceinline__ void cp_async16(uint32_t smem_dst, const void* gsrc) {
    asm volatile("cp.async.cg.shared.global [%0], [%1], 16;"
                 :: "r"(smem_dst), "l"(__cvta_generic_to_global(gsrc))
                 : "memory");
}
#define CP_COMMIT() asm volatile("cp.async.commit_group;" ::: "memory")
#define CP_WAIT2()  asm volatile("cp.async.wait_group 2;" ::: "memory")

__device__ __forceinline__ void mma_f16(float* c, const uint32_t* a,
                                        uint32_t b0, uint32_t b1) {
    asm volatile(
        "mma.sync.aligned.m16n8k16.row.col.f32.f16.f16.f32 "
        "{%0,%1,%2,%3}, {%4,%5,%6,%7}, {%8,%9}, {%0,%1,%2,%3};"
        : "+f"(c[0]), "+f"(c[1]), "+f"(c[2]), "+f"(c[3])
        : "r"(a[0]), "r"(a[1]), "r"(a[2]), "r"(a[3]), "r"(b0), "r"(b1));
}

__device__ __forceinline__ uint32_t h2(float lo, float hi) {
    __half2 h = __floats2half2_rn(lo, hi);
    return *(uint32_t*)&h;
}

// ---------------- prep kernels (unchanged from R4) ----------------
// cid fields: lane[0:5) s[5] it[6:9) kt[9:16) mb[16:22)
__global__ void __launch_bounds__(256)
prep_x_kernel(const float* __restrict__ X) {
    uint32_t cid = blockIdx.x * 256 + threadIdx.x;
    int lane = cid & 31;
    int s    = (cid >> 5) & 1;
    int it   = (cid >> 6) & 7;
    int kt   = (cid >> 9) & 127;
    int mb   = cid >> 16;
    int g = lane >> 2, tig = lane & 3;
    int m0 = mb * 128 + it * 16 + g;
    int k0 = kt * 32 + s * 16 + 2 * tig;
    const float* p0 = X + (size_t)m0 * K_ALL + k0;
    const float* p1 = X + (size_t)(m0 + 8) * K_ALL + k0;
    float2 v0 = *(const float2*)(p0);
    float2 v1 = *(const float2*)(p1);
    float2 v2 = *(const float2*)(p0 + 8);
    float2 v3 = *(const float2*)(p1 + 8);
    uint4 out;
    out.x = h2(v0.x, v0.y);
    out.y = h2(v1.x, v1.y);
    out.z = h2(v2.x, v2.y);
    out.w = h2(v3.x, v3.y);
    Xp[cid] = out;
}

// cid fields: lane[0:5) jt[5:9) kt[9:16) nb[16:23)
__global__ void __launch_bounds__(256)
prep_w_kernel(const float* __restrict__ W, const float* __restrict__ S) {
    uint32_t cid = blockIdx.x * 256 + threadIdx.x;
    int lane = cid & 31;
    int jt   = (cid >> 5) & 15;
    int kt   = (cid >> 9) & 127;
    int nb   = cid >> 16;
    int g = lane >> 2, tig = lane & 3;
    int n  = nb * 128 + jt * 8 + g;
    int kb = kt * 32 + 2 * tig;
    float sc = __ldg(S + (size_t)n * 32 + (kt >> 2));
    const float* p = W + (size_t)n * K_ALL + kb;
    float2 v0 = *(const float2*)(p);
    float2 v1 = *(const float2*)(p + 8);
    float2 v2 = *(const float2*)(p + 16);
    float2 v3 = *(const float2*)(p + 24);
    uint4 out;
    out.x = h2(v0.x * sc, v0.y * sc);
    out.y = h2(v1.x * sc, v1.y * sc);
    out.z = h2(v2.x * sc, v2.y * sc);
    out.w = h2(v3.x * sc, v3.y * sc);
    Wp[cid] = out;
}

// ---------------- GEMM ----------------
extern __shared__ __align__(1024) char smem_raw[];

__device__ __forceinline__ void load_tile(const uint4* __restrict__ Ablk,
                                          const uint4* __restrict__ Bblk,
                                          char* stage, int tid) {
    uint32_t sb = (uint32_t)__cvta_generic_to_shared(stage);
    #pragma unroll
    for (int i = 0; i < 4; i++)
        cp_async16(sb + (tid + i * THREADS) * 16, Ablk + tid + i * THREADS);
    #pragma unroll
    for (int i = 0; i < 4; i++)
        cp_async16(sb + (tid + (4 + i) * THREADS) * 16, Bblk + tid + i * THREADS);
}

__global__ void __launch_bounds__(THREADS, 2)
fp8linear_hmma_kernel(const float* __restrict__ BIAS,
                      float* __restrict__ OUT) {
    const int tid = threadIdx.x;
    const int lane = tid & 31;
    const int wid = tid >> 5;      // 0..3
    const int wm = wid & 1;        // 2 x 64 rows
    const int wn = wid >> 1;       // 2 x 64 cols (8 n8-tiles)
    const int g = lane >> 2;
    const int tig = lane & 3;

    // rasterization: GROUP_M=16
    int pid = blockIdx.x;
    int group = pid >> 11;
    int pid_loc = pid & 2047;
    int pid_m = group * 16 + (pid_loc & 15);
    int pid_n = pid_loc >> 4;

    const uint4* Abase = Xp + (size_t)pid_m * 128 * 512;   // 512 uint4 per kt
    const uint4* Bbase = Wp + (size_t)pid_n * 128 * 512;

    float acc[4][8][4];
    #pragma unroll
    for (int i = 0; i < 4; i++)
        #pragma unroll
        for (int j = 0; j < 8; j++)
            #pragma unroll
            for (int q = 0; q < 4; q++) acc[i][j][q] = 0.0f;

    #pragma unroll
    for (int p = 0; p < 3; p++) {
        load_tile(Abase + p * 512, Bbase + p * 512,
                  smem_raw + p * STAGE_BYTES, tid);
        CP_COMMIT();
    }

    for (int kt = 0; kt < NKT; kt++) {
        CP_WAIT2();
        __syncthreads();
        if (kt + 3 < NKT)
            load_tile(Abase + (kt + 3) * 512, Bbase + (kt + 3) * 512,
                      smem_raw + ((kt + 3) & 3) * STAGE_BYTES, tid);
        CP_COMMIT();

        const char* stg = smem_raw + (kt & 3) * STAGE_BYTES;
        const uint4* As = (const uint4*)stg;                 // 512 chunks
        const uint4* Bs = (const uint4*)(stg + 8192);

        // B fragments: 8 n8-tiles, one v4 covers both k16 halves
        uint4 bfr[8];
        #pragma unroll
        for (int j = 0; j < 8; j++)
            bfr[j] = Bs[(wn * 8 + j) * 32 + lane];

        #pragma unroll
        for (int s = 0; s < 2; s++) {
            uint4 afr[4];
            #pragma unroll
            for (int i = 0; i < 4; i++)
                afr[i] = As[((wm * 4 + i) * 2 + s) * 32 + lane];
            #pragma unroll
            for (int i = 0; i < 4; i++) {
                #pragma unroll
                for (int j = 0; j < 8; j++) {
                    uint32_t b0 = s ? bfr[j].z : bfr[j].x;
                    uint32_t b1 = s ? bfr[j].w : bfr[j].y;
                    mma_f16(acc[i][j], (const uint32_t*)&afr[i], b0, b1);
                }
            }
        }
    }

    // ---------------- epilogue: bias + store ----------------
    #pragma unroll
    for (int j = 0; j < 8; j++) {
        int col = pid_n * TN + wn * 64 + j * 8 + tig * 2;
        float2 bb = *(const float2*)(BIAS + col);
        #pragma unroll
        for (int i = 0; i < 4; i++) {
            int row0 = pid_m * TM + wm * 64 + i * 16 + g;
            float2 o0, o1;
            o0.x = acc[i][j][0] + bb.x;
            o0.y = acc[i][j][1] + bb.y;
            o1.x = acc[i][j][2] + bb.x;
            o1.y = acc[i][j][3] + bb.y;
            *(float2*)(OUT + (size_t)row0 * N_ALL + col) = o0;
            *(float2*)(OUT + (size_t)(row0 + 8) * N_ALL + col) = o1;
        }
    }
}

// ---------------- launch ----------------
extern "C" void kernel_launch(void* const* d_in, const int* in_sizes, int n_in,
                              void* d_out, int out_size) {
    const float* x = (const float*)d_in[0];      // [4,2048,4096]
    const float* qw = (const float*)d_in[1];     // [16384,4096]
    const float* sc = (const float*)d_in[2];     // [16384,32]
    const float* bias = (const float*)d_in[3];   // [16384]
    float* out = (float*)d_out;                  // [4,2048,16384]

    prep_x_kernel<<<4194304 / 256, 256>>>(x);
    prep_w_kernel<<<8388608 / 256, 256>>>(qw, sc);

    cudaFuncSetAttribute(fp8linear_hmma_kernel,
                         cudaFuncAttributeMaxDynamicSharedMemorySize, SMEM_TOTAL);
    int grid = (M_ALL / TM) * (N_ALL / TN);      // 8192
    fp8linear_hmma_kernel<<<grid, THREADS, SMEM_TOTAL>>>(bias, out);
}